// round 2
// baseline (speedup 1.0000x reference)
#include <cuda_runtime.h>
#include <cstdint>

// ---------------------------------------------------------------------------
// EnsembleHead: out = softmax_t( LSTM( (x @ Wfc^T + bfc) @ Wih^T + bih + bhh ) @ Wlast^T + blast )
// B=1024, N=512, D_IN=30, H=64, 4H=256
//
// Plan:
//   prep kernel: W_comb = Wih @ Wfc  (256x30), b_comb = Wih@bfc + bih + bhh,
//                plus repack W_hh -- all into paired [dpair][j][2] layouts.
//   main kernel: 128 persistent blocks x 256 threads; block owns 8 batch rows.
//                Thread j computes gate-preact j for all 8 rows using packed
//                f32x2 FMAs (rows paired). 512-step recurrence, logits + softmax
//                fully fused. Weights live in SMEM.
// ---------------------------------------------------------------------------

#define Bsz   1024
#define Nseq  512
#define DIN   30
#define Hdim  64
#define G4H   256
#define RPB   8            // batch rows per block
#define NBLK  (Bsz / RPB)  // 128

// device scratch (prep kernel outputs)
__device__ float g_wc2[15 * 512];    // [dp][j][2] : W_comb^T paired over d
__device__ float g_whh2[32 * 512];   // [kp][j][2] : W_hh paired over k
__device__ float g_bcomb[G4H];

// ---------------- f32x2 helpers ----------------
__device__ __forceinline__ unsigned long long pk2(float a) {
    unsigned long long r;
    asm("mov.b64 %0, {%1, %1};" : "=l"(r) : "f"(a));
    return r;
}
__device__ __forceinline__ unsigned long long ffma2(unsigned long long a,
                                                    unsigned long long b,
                                                    unsigned long long c) {
    unsigned long long d;
    asm("fma.rn.f32x2 %0, %1, %2, %3;" : "=l"(d) : "l"(a), "l"(b), "l"(c));
    return d;
}
__device__ __forceinline__ float lo2(unsigned long long v) {
    return __uint_as_float((unsigned)(v & 0xffffffffull));
}
__device__ __forceinline__ float hi2(unsigned long long v) {
    return __uint_as_float((unsigned)(v >> 32));
}

// ---------------- fast activations (MUFU EX2 + RCP, ~1e-7 rel err) ----------
__device__ __forceinline__ float ex2a(float x) {
    float r; asm("ex2.approx.f32 %0, %1;" : "=f"(r) : "f"(x)); return r;
}
__device__ __forceinline__ float rcpa(float x) {
    float r; asm("rcp.approx.f32 %0, %1;" : "=f"(r) : "f"(x)); return r;
}
__device__ __forceinline__ float sigm(float x) {
    return rcpa(1.0f + ex2a(-1.4426950408889634f * x));
}
__device__ __forceinline__ float tanh_(float x) {
    return fmaf(2.0f, rcpa(1.0f + ex2a(-2.8853900817779268f * x)), -1.0f);
}

// ---------------------------------------------------------------------------
// prep: fold FC into the input-side gate map; repack everything paired.
// one block, 256 threads (thread j = gate index)
// ---------------------------------------------------------------------------
__global__ void prep_kernel(const float* __restrict__ Wfc,   // (64,30)
                            const float* __restrict__ bfc,   // (64)
                            const float* __restrict__ Wih,   // (256,64)
                            const float* __restrict__ Whh,   // (256,64)
                            const float* __restrict__ bih,   // (256)
                            const float* __restrict__ bhh)   // (256)
{
    int j = threadIdx.x;

    float acc[DIN];
#pragma unroll
    for (int d = 0; d < DIN; ++d) acc[d] = 0.0f;
    float bs = bih[j] + bhh[j];

#pragma unroll 8
    for (int k = 0; k < Hdim; ++k) {
        float w = Wih[j * Hdim + k];
        bs = fmaf(w, bfc[k], bs);
#pragma unroll
        for (int d = 0; d < DIN; ++d)
            acc[d] = fmaf(w, Wfc[k * DIN + d], acc[d]);
    }
    g_bcomb[j] = bs;
#pragma unroll
    for (int d = 0; d < DIN; ++d)
        g_wc2[(d >> 1) * 512 + (j << 1) + (d & 1)] = acc[d];
#pragma unroll
    for (int k = 0; k < Hdim; ++k)
        g_whh2[(k >> 1) * 512 + (j << 1) + (k & 1)] = Whh[j * Hdim + k];
}

// ---------------------------------------------------------------------------
// main fused kernel
// shared layout (floats):
//   OFF_WC  = 0      (7680)   W_comb paired
//   OFF_WHH = 7680   (16384)  W_hh paired
//   OFF_XS  = 24064  (480)    x stage, 2 bufs x [d][8 rows]
//   OFF_G   = 24544  (2048)   activated gates [j][8 rows]
//   OFF_H   = 26592  (512)    h [k][8 rows]
//   OFF_WL  = 27104  (64)     W_last
//   OFF_LOG = 27168  (4096)   logits [r][512]
//   OFF_BL  = 31264  (1)      b_last
// ---------------------------------------------------------------------------
#define OFF_WC  0
#define OFF_WHH 7680
#define OFF_XS  24064
#define OFF_G   24544
#define OFF_H   26592
#define OFF_WL  27104
#define OFF_LOG 27168
#define OFF_BL  31264
#define SMEM_FLOATS 31268
#define SMEM_BYTES  (SMEM_FLOATS * 4)

__global__ void __launch_bounds__(256, 1)
lstm_fused_kernel(const float* __restrict__ X,      // (B, N, 30)
                  const float* __restrict__ Wlast,  // (1,64)
                  const float* __restrict__ blast,  // (1)
                  float* __restrict__ out)          // (B, N)
{
    extern __shared__ float s[];
    const int tid  = threadIdx.x;
    const int j    = tid;
    const int w    = tid >> 5;   // warp id = owned batch-row
    const int lane = tid & 31;
    const int b0   = blockIdx.x * RPB;

    // ---- stage weights into SMEM ----
    for (int i = tid; i < 7680;  i += 256) s[OFF_WC + i]  = g_wc2[i];
    for (int i = tid; i < 16384; i += 256) s[OFF_WHH + i] = g_whh2[i];
    if (tid < Hdim) s[OFF_WL + tid] = Wlast[tid];
    if (tid == 0)   s[OFF_BL] = blast[0];
    for (int i = tid; i < 512; i += 256) s[OFF_H + i] = 0.0f;   // h0 = 0

    const unsigned long long bias2 = pk2(g_bcomb[j]);

    // preload x for t=0
    if (lane < DIN)
        s[OFF_XS + (lane << 3) + w] = X[(size_t)(b0 + w) * (Nseq * DIN) + lane];
    __syncthreads();

    // per-thread LSTM cell state (threads < 128: tid&63 = hidden k, tid>>6 = row half)
    float cc0 = 0.0f, cc1 = 0.0f, cc2 = 0.0f, cc3 = 0.0f;

    const float2* wcp = (const float2*)&s[OFF_WC];
    const float2* whp = (const float2*)&s[OFF_WHH];

    for (int t = 0; t < Nseq; ++t) {
        const int buf  = t & 1;
        const int nbuf = buf ^ 1;

        // prefetch next x (LDG issued early, consumed late)
        float xv = 0.0f;
        const bool pf = (lane < DIN) && (t < Nseq - 1);
        if (pf) xv = X[(size_t)(b0 + w) * (Nseq * DIN) + (size_t)(t + 1) * DIN + lane];

        // ---- gate preactivations: thread j, 8 rows paired into 4 f32x2 accs
        unsigned long long a0 = bias2, a1 = bias2, a2 = bias2, a3 = bias2;

        const ulonglong2* xq = (const ulonglong2*)&s[OFF_XS + buf * 240];
#pragma unroll
        for (int dp = 0; dp < 15; ++dp) {
            float2 wv = wcp[dp * 256 + j];
            unsigned long long wA = pk2(wv.x), wB = pk2(wv.y);
            ulonglong2 p0 = xq[4 * dp + 0];
            ulonglong2 p1 = xq[4 * dp + 1];
            ulonglong2 p2 = xq[4 * dp + 2];
            ulonglong2 p3 = xq[4 * dp + 3];
            a0 = ffma2(p0.x, wA, a0); a1 = ffma2(p0.y, wA, a1);
            a2 = ffma2(p1.x, wA, a2); a3 = ffma2(p1.y, wA, a3);
            a0 = ffma2(p2.x, wB, a0); a1 = ffma2(p2.y, wB, a1);
            a2 = ffma2(p3.x, wB, a2); a3 = ffma2(p3.y, wB, a3);
        }

        const ulonglong2* hq = (const ulonglong2*)&s[OFF_H];
#pragma unroll
        for (int kp = 0; kp < 32; ++kp) {
            float2 wv = whp[kp * 256 + j];
            unsigned long long wA = pk2(wv.x), wB = pk2(wv.y);
            ulonglong2 p0 = hq[4 * kp + 0];
            ulonglong2 p1 = hq[4 * kp + 1];
            ulonglong2 p2 = hq[4 * kp + 2];
            ulonglong2 p3 = hq[4 * kp + 3];
            a0 = ffma2(p0.x, wA, a0); a1 = ffma2(p0.y, wA, a1);
            a2 = ffma2(p1.x, wA, a2); a3 = ffma2(p1.y, wA, a3);
            a0 = ffma2(p2.x, wB, a0); a1 = ffma2(p2.y, wB, a1);
            a2 = ffma2(p3.x, wB, a2); a3 = ffma2(p3.y, wB, a3);
        }

        // stage next x into the other buffer
        if (pf) s[OFF_XS + nbuf * 240 + (lane << 3) + w] = xv;

        // ---- activation (warp-uniform by gate quarter) ----
        float v0 = lo2(a0), v1 = hi2(a0), v2 = lo2(a1), v3 = hi2(a1);
        float v4 = lo2(a2), v5 = hi2(a2), v6 = lo2(a3), v7 = hi2(a3);
        const int q = j >> 6;   // 0:i 1:f 2:g 3:o
        float g0, g1, g2, g3, g4, g5, g6, g7;
        if (q == 2) {
            g0 = tanh_(v0); g1 = tanh_(v1); g2 = tanh_(v2); g3 = tanh_(v3);
            g4 = tanh_(v4); g5 = tanh_(v5); g6 = tanh_(v6); g7 = tanh_(v7);
        } else {
            g0 = sigm(v0); g1 = sigm(v1); g2 = sigm(v2); g3 = sigm(v3);
            g4 = sigm(v4); g5 = sigm(v5); g6 = sigm(v6); g7 = sigm(v7);
        }
        float4 s0 = make_float4(g0, g1, g2, g3);
        float4 s1 = make_float4(g4, g5, g6, g7);
        *(float4*)&s[OFF_G + (j << 3)]     = s0;
        *(float4*)&s[OFF_G + (j << 3) + 4] = s1;

        __syncthreads();

        // ---- cell update: 128 threads, thread = (hidden k, row half) ----
        if (tid < 128) {
            const int k  = tid & 63;
            const int ro = (tid >> 6) << 2;   // 0 or 4
            float4 gi = *(const float4*)&s[OFF_G + ((      k) << 3) + ro];
            float4 gf = *(const float4*)&s[OFF_G + (( 64 + k) << 3) + ro];
            float4 gg = *(const float4*)&s[OFF_G + ((128 + k) << 3) + ro];
            float4 go = *(const float4*)&s[OFF_G + ((192 + k) << 3) + ro];
            cc0 = fmaf(gf.x, cc0, gi.x * gg.x);
            cc1 = fmaf(gf.y, cc1, gi.y * gg.y);
            cc2 = fmaf(gf.z, cc2, gi.z * gg.z);
            cc3 = fmaf(gf.w, cc3, gi.w * gg.w);
            float4 hv;
            hv.x = go.x * tanh_(cc0);
            hv.y = go.y * tanh_(cc1);
            hv.z = go.z * tanh_(cc2);
            hv.w = go.w * tanh_(cc3);
            *(float4*)&s[OFF_H + (k << 3) + ro] = hv;
        }
        __syncthreads();

        // ---- logit for row w: dot(h_row, Wlast) via warp reduce ----
        {
            float p = s[OFF_H + (lane << 3) + w]        * s[OFF_WL + lane] +
                      s[OFF_H + ((lane + 32) << 3) + w] * s[OFF_WL + lane + 32];
            p += __shfl_down_sync(0xffffffffu, p, 16);
            p += __shfl_down_sync(0xffffffffu, p, 8);
            p += __shfl_down_sync(0xffffffffu, p, 4);
            p += __shfl_down_sync(0xffffffffu, p, 2);
            p += __shfl_down_sync(0xffffffffu, p, 1);
            if (lane == 0) s[OFF_LOG + w * Nseq + t] = p + s[OFF_BL];
        }
    }

    __syncthreads();

    // ---- softmax over t for row w (one warp per row) ----
    {
        float v[16];
#pragma unroll
        for (int i = 0; i < 16; ++i)
            v[i] = s[OFF_LOG + w * Nseq + i * 32 + lane];
        float m = v[0];
#pragma unroll
        for (int i = 1; i < 16; ++i) m = fmaxf(m, v[i]);
        m = fmaxf(m, __shfl_xor_sync(0xffffffffu, m, 16));
        m = fmaxf(m, __shfl_xor_sync(0xffffffffu, m, 8));
        m = fmaxf(m, __shfl_xor_sync(0xffffffffu, m, 4));
        m = fmaxf(m, __shfl_xor_sync(0xffffffffu, m, 2));
        m = fmaxf(m, __shfl_xor_sync(0xffffffffu, m, 1));

        float e[16], sum = 0.0f;
#pragma unroll
        for (int i = 0; i < 16; ++i) {
            e[i] = ex2a((v[i] - m) * 1.4426950408889634f);
            sum += e[i];
        }
        sum += __shfl_xor_sync(0xffffffffu, sum, 16);
        sum += __shfl_xor_sync(0xffffffffu, sum, 8);
        sum += __shfl_xor_sync(0xffffffffu, sum, 4);
        sum += __shfl_xor_sync(0xffffffffu, sum, 2);
        sum += __shfl_xor_sync(0xffffffffu, sum, 1);
        const float inv = 1.0f / sum;

        float* orow = out + (size_t)(b0 + w) * Nseq;
#pragma unroll
        for (int i = 0; i < 16; ++i)
            orow[i * 32 + lane] = e[i] * inv;
    }
}

// ---------------------------------------------------------------------------
extern "C" void kernel_launch(void* const* d_in, const int* in_sizes, int n_in,
                              void* d_out, int out_size) {
    const float* x     = (const float*)d_in[0];
    const float* Wfc   = (const float*)d_in[1];
    const float* bfc   = (const float*)d_in[2];
    const float* Wih   = (const float*)d_in[3];
    const float* Whh   = (const float*)d_in[4];
    const float* bih   = (const float*)d_in[5];
    const float* bhh   = (const float*)d_in[6];
    const float* Wlast = (const float*)d_in[7];
    const float* blast = (const float*)d_in[8];
    float* out = (float*)d_out;

    cudaFuncSetAttribute(lstm_fused_kernel,
                         cudaFuncAttributeMaxDynamicSharedMemorySize, SMEM_BYTES);

    prep_kernel<<<1, 256>>>(Wfc, bfc, Wih, Whh, bih, bhh);
    lstm_fused_kernel<<<NBLK, 256, SMEM_BYTES>>>(x, Wlast, blast, out);
}

// round 3
// speedup vs baseline: 1.2643x; 1.2643x over previous
#include <cuda_runtime.h>
#include <cstdint>

// ---------------------------------------------------------------------------
// EnsembleHead fused: FC folded into gate map; 512-step LSTM; logits+softmax.
// B=1024, N=512, D_IN=30, H=64, 4H=256.
//
// R2 design: weights live in REGISTERS (47 prepacked f32x2 per thread),
// f32x2 lanes pair the reduction dim (even/odd k), RPB=4 rows per block,
// grid=256 blocks x 256 threads, 2 CTAs/SM.
// ---------------------------------------------------------------------------

typedef unsigned long long ull;

#define Bsz   1024
#define Nseq  512
#define DIN   30
#define Hdim  64
#define RPB   4
#define NBLK  (Bsz / RPB)   // 256
#define MX    15            // x d-pairs
#define MH    32            // h k-pairs
#define MT    (MX + MH)     // 47

// prep outputs
__device__ ull   g_wpk[MT * 256];   // [m][j] : packed (w_even, w_odd)
__device__ float g_bcomb[256];

// ---------------- helpers ----------------
__device__ __forceinline__ ull pkf2(float a, float b) {
    return (ull)__float_as_uint(a) | ((ull)__float_as_uint(b) << 32);
}
__device__ __forceinline__ ull ffma2(ull a, ull b, ull c) {
    ull d;
    asm("fma.rn.f32x2 %0, %1, %2, %3;" : "=l"(d) : "l"(a), "l"(b), "l"(c));
    return d;
}
__device__ __forceinline__ float sum2(ull v) {
    float lo, hi;
    asm("mov.b64 {%0, %1}, %2;" : "=f"(lo), "=f"(hi) : "l"(v));
    return lo + hi;
}
__device__ __forceinline__ float ex2a(float x) {
    float r; asm("ex2.approx.f32 %0, %1;" : "=f"(r) : "f"(x)); return r;
}
__device__ __forceinline__ float rcpa(float x) {
    float r; asm("rcp.approx.f32 %0, %1;" : "=f"(r) : "f"(x)); return r;
}
__device__ __forceinline__ float sigm(float x) {
    return rcpa(1.0f + ex2a(-1.4426950408889634f * x));
}
__device__ __forceinline__ float tanh_(float x) {
    return fmaf(2.0f, rcpa(1.0f + ex2a(-2.8853900817779268f * x)), -1.0f);
}

// ---------------------------------------------------------------------------
// prep: W_comb = Wih @ Wfc (256x30), b_comb = Wih@bfc + bih + bhh,
// pack reduction-dim pairs: m<15 -> (Wc[j][2m],Wc[j][2m+1]);
// m>=15 -> (Whh[j][2(m-15)], Whh[j][2(m-15)+1]).
// ---------------------------------------------------------------------------
__global__ void prep_kernel(const float* __restrict__ Wfc,   // (64,30)
                            const float* __restrict__ bfc,   // (64)
                            const float* __restrict__ Wih,   // (256,64)
                            const float* __restrict__ Whh,   // (256,64)
                            const float* __restrict__ bih,   // (256)
                            const float* __restrict__ bhh)   // (256)
{
    int j = threadIdx.x;

    float acc[DIN];
#pragma unroll
    for (int d = 0; d < DIN; ++d) acc[d] = 0.0f;
    float bs = bih[j] + bhh[j];

#pragma unroll 8
    for (int k = 0; k < Hdim; ++k) {
        float w = Wih[j * Hdim + k];
        bs = fmaf(w, bfc[k], bs);
#pragma unroll
        for (int d = 0; d < DIN; ++d)
            acc[d] = fmaf(w, Wfc[k * DIN + d], acc[d]);
    }
    g_bcomb[j] = bs;
#pragma unroll
    for (int dp = 0; dp < MX; ++dp)
        g_wpk[dp * 256 + j] = pkf2(acc[2 * dp], acc[2 * dp + 1]);
#pragma unroll
    for (int m = 0; m < MH; ++m)
        g_wpk[(MX + m) * 256 + j] = pkf2(Whh[j * Hdim + 2 * m],
                                         Whh[j * Hdim + 2 * m + 1]);
}

// ---------------------------------------------------------------------------
// shared layout (floats); all vector-load bases 16B aligned
// ---------------------------------------------------------------------------
#define OFF_XS   0      // 2 x 120 : x stage [dp][4 rows][2], double-buffered
#define OFF_H    240    // 256     : h [m][4 rows][2]
#define OFF_G    496    // 1024    : activated gates [r][256]
#define OFF_WL   1520   // 64      : W_last
#define OFF_PART 1584   // 8       : per-warp logit partials
#define OFF_LOG  1592   // 2048    : logits [r][512]
#define SMEM_FLOATS 3640

__global__ void __launch_bounds__(256, 2)
lstm_fused_kernel(const float* __restrict__ X,      // (B, N, 30)
                  const float* __restrict__ Wlast,  // (1,64)
                  const float* __restrict__ blast,  // (1)
                  float* __restrict__ out)          // (B, N)
{
    __shared__ __align__(16) float s[SMEM_FLOATS];
    const int tid  = threadIdx.x;
    const int lane = tid & 31;
    const int wid  = tid >> 5;
    const int b0   = blockIdx.x * RPB;

    if (tid < Hdim) s[OFF_WL + tid] = Wlast[tid];
    s[OFF_H + tid] = 0.0f;   // h0 = 0 (256 floats)

    // ---- loop-invariant weights into registers ----
    ull wreg[MT];
#pragma unroll
    for (int m = 0; m < MT; ++m) wreg[m] = g_wpk[m * 256 + tid];
    const float bias = g_bcomb[tid];
    const float blv  = blast[0];

    // ---- x prefetch role: thread < 120 owns (row, d) ----
    const int  prow = tid / DIN;
    const int  pd   = tid - prow * DIN;
    const bool px   = tid < RPB * DIN;
    const float* xp = X + (size_t)(b0 + prow) * (Nseq * DIN) + pd;
    const int  xsoff = (pd >> 1) * 8 + prow * 2 + (pd & 1);
    if (px) s[OFF_XS + xsoff] = xp[0];

    // ---- update role: thread = (row ur, hidden uk) ----
    const int ur = tid >> 6, uk = tid & 63;
    const int goff = OFF_G + ur * 256 + uk;
    const int hoff = OFF_H + (uk >> 1) * 8 + ur * 2 + (uk & 1);
    const int q = tid >> 6;   // gate quarter for activation
    __syncthreads();
    const float wlk = s[OFF_WL + uk];
    float cc = 0.0f;

    for (int t = 0; t < Nseq; ++t) {
        const int buf = t & 1;

        // combine previous step's logit partials (protected by last sync)
        if (t > 0 && tid < RPB)
            s[OFF_LOG + tid * Nseq + (t - 1)] =
                s[OFF_PART + 2 * tid] + s[OFF_PART + 2 * tid + 1] + blv;

        // prefetch x(t+1)
        float xv = 0.0f;
        const bool pf = px && (t + 1 < Nseq);
        if (pf) xv = xp[(t + 1) * DIN];

        // ---- gate matvec: 4 rows, even/odd-k lanes packed ----
        ull a0 = 0, a1 = 0, a2 = 0, a3 = 0;
        const ulonglong2* xq = (const ulonglong2*)(s + OFF_XS + buf * 120);
#pragma unroll
        for (int dp = 0; dp < MX; ++dp) {
            ulonglong2 pA = xq[2 * dp];       // rows 0,1
            ulonglong2 pB = xq[2 * dp + 1];   // rows 2,3
            ull w = wreg[dp];
            a0 = ffma2(pA.x, w, a0); a1 = ffma2(pA.y, w, a1);
            a2 = ffma2(pB.x, w, a2); a3 = ffma2(pB.y, w, a3);
        }
        const ulonglong2* hq = (const ulonglong2*)(s + OFF_H);
#pragma unroll
        for (int m = 0; m < MH; ++m) {
            ulonglong2 pA = hq[2 * m];
            ulonglong2 pB = hq[2 * m + 1];
            ull w = wreg[MX + m];
            a0 = ffma2(pA.x, w, a0); a1 = ffma2(pA.y, w, a1);
            a2 = ffma2(pB.x, w, a2); a3 = ffma2(pB.y, w, a3);
        }

        // stage next x into the other buffer
        if (pf) s[OFF_XS + (buf ^ 1) * 120 + xsoff] = xv;

        // ---- activation (warp-uniform by gate quarter) ----
        float v0 = sum2(a0) + bias;
        float v1 = sum2(a1) + bias;
        float v2 = sum2(a2) + bias;
        float v3 = sum2(a3) + bias;
        float g0, g1, g2, g3;
        if (q == 2) {
            g0 = tanh_(v0); g1 = tanh_(v1); g2 = tanh_(v2); g3 = tanh_(v3);
        } else {
            g0 = sigm(v0); g1 = sigm(v1); g2 = sigm(v2); g3 = sigm(v3);
        }
        s[OFF_G + 0 * 256 + tid] = g0;
        s[OFF_G + 1 * 256 + tid] = g1;
        s[OFF_G + 2 * 256 + tid] = g2;
        s[OFF_G + 3 * 256 + tid] = g3;

        __syncthreads();

        // ---- cell update: one (row, k) per thread ----
        {
            float gi = s[goff];
            float gf = s[goff + 64];
            float gg = s[goff + 128];
            float go = s[goff + 192];
            cc = fmaf(gf, cc, gi * gg);
            float hv = go * tanh_(cc);
            s[hoff] = hv;

            // logit partial: dot(h_row, Wlast) over this warp's 32 k's
            float p = hv * wlk;
            p += __shfl_down_sync(0xffffffffu, p, 16);
            p += __shfl_down_sync(0xffffffffu, p, 8);
            p += __shfl_down_sync(0xffffffffu, p, 4);
            p += __shfl_down_sync(0xffffffffu, p, 2);
            p += __shfl_down_sync(0xffffffffu, p, 1);
            if (lane == 0) s[OFF_PART + wid] = p;
        }
        __syncthreads();
    }

    // last logit
    if (tid < RPB)
        s[OFF_LOG + tid * Nseq + (Nseq - 1)] =
            s[OFF_PART + 2 * tid] + s[OFF_PART + 2 * tid + 1] + blv;
    __syncthreads();

    // ---- softmax over t: warp r handles row r ----
    if (wid < RPB) {
        float v[16];
#pragma unroll
        for (int i = 0; i < 16; ++i)
            v[i] = s[OFF_LOG + wid * Nseq + i * 32 + lane];
        float m = v[0];
#pragma unroll
        for (int i = 1; i < 16; ++i) m = fmaxf(m, v[i]);
        m = fmaxf(m, __shfl_xor_sync(0xffffffffu, m, 16));
        m = fmaxf(m, __shfl_xor_sync(0xffffffffu, m, 8));
        m = fmaxf(m, __shfl_xor_sync(0xffffffffu, m, 4));
        m = fmaxf(m, __shfl_xor_sync(0xffffffffu, m, 2));
        m = fmaxf(m, __shfl_xor_sync(0xffffffffu, m, 1));

        float e[16], sum = 0.0f;
#pragma unroll
        for (int i = 0; i < 16; ++i) {
            e[i] = ex2a((v[i] - m) * 1.4426950408889634f);
            sum += e[i];
        }
        sum += __shfl_xor_sync(0xffffffffu, sum, 16);
        sum += __shfl_xor_sync(0xffffffffu, sum, 8);
        sum += __shfl_xor_sync(0xffffffffu, sum, 4);
        sum += __shfl_xor_sync(0xffffffffu, sum, 2);
        sum += __shfl_xor_sync(0xffffffffu, sum, 1);
        const float inv = 1.0f / sum;

        float* orow = out + (size_t)(b0 + wid) * Nseq;
#pragma unroll
        for (int i = 0; i < 16; ++i)
            orow[i * 32 + lane] = e[i] * inv;
    }
}

// ---------------------------------------------------------------------------
extern "C" void kernel_launch(void* const* d_in, const int* in_sizes, int n_in,
                              void* d_out, int out_size) {
    const float* x     = (const float*)d_in[0];
    const float* Wfc   = (const float*)d_in[1];
    const float* bfc   = (const float*)d_in[2];
    const float* Wih   = (const float*)d_in[3];
    const float* Whh   = (const float*)d_in[4];
    const float* bih   = (const float*)d_in[5];
    const float* bhh   = (const float*)d_in[6];
    const float* Wlast = (const float*)d_in[7];
    const float* blast = (const float*)d_in[8];
    float* out = (float*)d_out;

    prep_kernel<<<1, 256>>>(Wfc, bfc, Wih, Whh, bih, bhh);
    lstm_fused_kernel<<<NBLK, 256>>>(x, Wlast, blast, out);
}